// round 17
// baseline (speedup 1.0000x reference)
#include <cuda_runtime.h>
#include <cuda_fp16.h>

// Problem constants (fixed by the reference)
#define NN 50000          // nodes
#define NE 800000         // edges
#define DD 96             // feature dim
#define D4 24             // DD / 4 (float4 groups)
#define NB 196            // ceil(NN / 256) scan blocks

// ---------------- scratch (device globals; no allocation allowed) -----------
// RULE (learned R10-R13): NEVER pass these symbols as kernel arguments from
// host code — the host-side shadow address is silently GPU-accessible via
// ATS/NVLink-C2C on GB300 and runs at host-memory speed (13x regression).
// Kernels reference them directly in device code (template MODE selects).
__device__ __half g_hx[NN * DD];   // intermediate activations, fp16 (ns-scaled)
__device__ float  g_m[NN * DD];    // aggregated messages (already * norm_dst)
__device__ int    g_od[NN];        // out degree (src side)
__device__ int    g_id[NN];        // in degree (dst side)
__device__ float  g_ns[NN];        // out_deg^-1/2
__device__ float  g_nd[NN];        // in_deg^-1/2
__device__ int    g_off[NN + 1];   // CSR offsets (by dst)
__device__ int    g_cur[NN];       // CSR fill cursors
__device__ int    g_eidx[NE];      // src ids grouped by dst
__device__ int    g_is64;          // 1 if index arrays are int64, 0 if int32
__device__ int    g_bsum[NB];      // per-block in-degree sums

__device__ __forceinline__ int load_idx(const void* p, int e, int is64) {
    if (is64) return (int)((const long long*)p)[e];
    return ((const int*)p)[e];
}

// ---------------- init: zero degrees + dtype probe in block 0 ---------------
// int32 ids read as int64 pack two ids per word -> value >= 2^32 unless the
// high id is 0 (prob 1/50000 per sample; 256 samples -> certain detection).
__global__ void k_init(const void* src, const void* dst) {
    int i = blockIdx.x * blockDim.x + threadIdx.x;
    if (i < NN) { g_od[i] = 0; g_id[i] = 0; }
    if (blockIdx.x == 0) {
        __shared__ int bad;
        if (threadIdx.x == 0) bad = 0;
        __syncthreads();
        long long v1 = ((const long long*)src)[threadIdx.x];
        long long v2 = ((const long long*)dst)[threadIdx.x];
        if (v1 < 0 || v1 >= NN || v2 < 0 || v2 >= NN) bad = 1;
        __syncthreads();
        if (threadIdx.x == 0) g_is64 = bad ? 0 : 1;
    }
}

__global__ void k_deg(const void* __restrict__ src, const void* __restrict__ dst) {
    int e = blockIdx.x * blockDim.x + threadIdx.x;
    if (e < NE) {
        int is64 = g_is64;
        atomicAdd(&g_od[load_idx(src, e, is64)], 1);
        atomicAdd(&g_id[load_idx(dst, e, is64)], 1);
    }
}

// ---------------- norms + per-block in-degree sums (coalesced) --------------
__global__ void k_norm_bsum() {
    int i = blockIdx.x * blockDim.x + threadIdx.x;
    int lane = threadIdx.x & 31, w = threadIdx.x >> 5;
    int idg = 0;
    if (i < NN) {
        int odg = g_od[i];
        idg = g_id[i];
        g_ns[i] = rsqrtf((float)max(odg, 1));
        g_nd[i] = rsqrtf((float)max(idg, 1));
    }
    int s = idg;
#pragma unroll
    for (int o = 16; o > 0; o >>= 1) s += __shfl_down_sync(0xffffffffu, s, o);
    __shared__ int ws[8];
    if (lane == 0) ws[w] = s;
    __syncthreads();
    if (threadIdx.x == 0) {
        int tot = 0;
#pragma unroll
        for (int k = 0; k < 8; k++) tot += ws[k];
        g_bsum[blockIdx.x] = tot;
    }
}

// ---------------- per-node CSR offsets (block scan + own prefix over bsum) ---
__global__ void k_offsets() {
    int i = blockIdx.x * blockDim.x + threadIdx.x;
    int lane = threadIdx.x & 31, w = threadIdx.x >> 5;
    __shared__ int ws[8];
    __shared__ int pre_s;

    // Block prefix: sum of g_bsum[0..blockIdx.x) computed locally (<=196 ints;
    // cheaper than a separate scan launch).
    int pre = 0;
    for (int t = threadIdx.x; t < blockIdx.x; t += 256) pre += g_bsum[t];
#pragma unroll
    for (int o = 16; o > 0; o >>= 1) pre += __shfl_down_sync(0xffffffffu, pre, o);
    if (lane == 0) ws[w] = pre;
    __syncthreads();
    if (threadIdx.x == 0) {
        int tot = 0;
#pragma unroll
        for (int k = 0; k < 8; k++) tot += ws[k];
        pre_s = tot;
    }
    __syncthreads();
    int block_base = pre_s;
    __syncthreads();   // ws reused below

    // Intra-block exclusive scan of in-degrees
    int v = (i < NN) ? g_id[i] : 0;
    int x = v;
#pragma unroll
    for (int o = 1; o < 32; o <<= 1) {
        int u = __shfl_up_sync(0xffffffffu, x, o);
        if (lane >= o) x += u;
    }
    if (lane == 31) ws[w] = x;
    __syncthreads();
    if (w == 0 && lane < 8) {
        int y = ws[lane];
#pragma unroll
        for (int o = 1; o < 8; o <<= 1) {
            int u = __shfl_up_sync(0x000000ffu, y, o);
            if (lane >= o) y += u;
        }
        ws[lane] = y;
    }
    __syncthreads();
    int ex = x - v + (w > 0 ? ws[w - 1] : 0);
    int off = block_base + ex;
    if (i < NN) { g_off[i] = off; g_cur[i] = off; }
    if (i == NN - 1) g_off[NN] = off + v;   // == NE
}

__global__ void k_fill(const void* __restrict__ src, const void* __restrict__ dst) {
    int e = blockIdx.x * blockDim.x + threadIdx.x;
    if (e < NE) {
        int is64 = g_is64;
        int s = load_idx(src, e, is64);
        int d = load_idx(dst, e, is64);
        int pos = atomicAdd(&g_cur[d], 1);
        g_eidx[pos] = s;
    }
}

// ---------------- CSR gather: m[d] = nd[d] * sum_{e in CSR[d]} x[src[e]] -----
// One warp per dst node. Lanes batch-load 32 edge indices (coalesced), then
// shuffle-broadcast each src; each lane accumulates 3 features (lane, +32, +64).
// MODE 0 (layer 0): read external fp32 h, scale each message by g_ns[src].
// MODE 1 (layers 1-2): read internal fp16 g_hx (already ns-scaled) — halves
// the dominant L2 read traffic vs fp32.
template <int MODE>
__global__ __launch_bounds__(256) void k_gather(const float* __restrict__ hext) {
    int warp = (blockIdx.x * blockDim.x + threadIdx.x) >> 5;
    int lane = threadIdx.x & 31;
    if (warp >= NN) return;
    int beg = g_off[warp];
    int end = g_off[warp + 1];
    float a0 = 0.f, a1 = 0.f, a2 = 0.f;
    for (int base = beg; base < end; base += 32) {
        int got = min(32, end - base);
        int idx = (base + lane < end) ? g_eidx[base + lane] : 0;
        float nsv = 0.f;
        if (MODE == 0) nsv = (base + lane < end) ? g_ns[idx] : 0.f;
#pragma unroll 4
        for (int j = 0; j < got; j++) {
            int s = __shfl_sync(0xffffffffu, idx, j);
            if (MODE == 0) {
                const float* xp = hext + s * DD;
                float f = __shfl_sync(0xffffffffu, nsv, j);
                a0 = fmaf(xp[lane],      f, a0);
                a1 = fmaf(xp[lane + 32], f, a1);
                a2 = fmaf(xp[lane + 64], f, a2);
            } else {
                const __half* xp = g_hx + s * DD;
                a0 += __half2float(xp[lane]);
                a1 += __half2float(xp[lane + 32]);
                a2 += __half2float(xp[lane + 64]);
            }
        }
    }
    float nd = g_nd[warp];
    float* mp = g_m + warp * DD;
    mp[lane]      = a0 * nd;
    mp[lane + 32] = a1 * nd;
    mp[lane + 64] = a2 * nd;
}

// ---------------- GEMM + bias + relu (+ fused norm_src pre-scale) -----------
// out[i][j] = relu(b[j] + sum_k m[i][k] * W[k][j]).
// LAST=0: write internal fp16 g_hx, multiplied by norm_src[i] (pre-scaled
//         input for the next layer's gather). Never pass g_hx from host!
// LAST=1: write external fp32 buffer (final output), no pre-scale.
// Block: 192 threads, 32-row tile. W (36KB) + M-tile (12KB) in smem (48KB).
template <int LAST>
__global__ __launch_bounds__(192) void k_gemm(const float* __restrict__ W,
                                              const float* __restrict__ B,
                                              float* __restrict__ outext) {
    __shared__ float Ws[DD * DD];   // 36864 B
    __shared__ float Ms[32 * DD];   // 12288 B
    int tid = threadIdx.x;
    int row0 = blockIdx.x * 32;

    const float4* W4 = (const float4*)W;
    float4* Ws4 = (float4*)Ws;
#pragma unroll
    for (int i = 0; i < 12; i++) Ws4[tid + i * 192] = W4[tid + i * 192];

#pragma unroll
    for (int i = 0; i < 4; i++) {
        int li = tid + i * 192;          // 0..767
        int r = li / D4;
        int c4 = li - r * D4;
        int row = row0 + r;
        float4 v = make_float4(0.f, 0.f, 0.f, 0.f);
        if (row < NN) v = ((const float4*)g_m)[row * D4 + c4];
        ((float4*)Ms)[li] = v;
    }
    __syncthreads();

    int ct = tid % 24;    // column group (4 cols)
    int rt = tid / 24;    // row group (4 rows)

    float acc[4][4];
#pragma unroll
    for (int rr = 0; rr < 4; rr++)
#pragma unroll
        for (int cc = 0; cc < 4; cc++) acc[rr][cc] = 0.f;

#pragma unroll
    for (int k = 0; k < DD; k += 4) {
        float wreg[4][4];
#pragma unroll
        for (int kk = 0; kk < 4; kk++)
            *(float4*)(&wreg[kk][0]) = *(const float4*)(Ws + (k + kk) * DD + ct * 4);
#pragma unroll
        for (int rr = 0; rr < 4; rr++) {
            float mreg[4];
            *(float4*)mreg = *(const float4*)(Ms + (rt * 4 + rr) * DD + k);
#pragma unroll
            for (int kk = 0; kk < 4; kk++)
#pragma unroll
                for (int cc = 0; cc < 4; cc++)
                    acc[rr][cc] = fmaf(mreg[kk], wreg[kk][cc], acc[rr][cc]);
        }
    }

    float bb[4];
    *(float4*)bb = *(const float4*)(B + ct * 4);
#pragma unroll
    for (int rr = 0; rr < 4; rr++) {
        int row = row0 + rt * 4 + rr;
        if (row < NN) {
            float oo[4];
#pragma unroll
            for (int cc = 0; cc < 4; cc++)
                oo[cc] = fmaxf(acc[rr][cc] + bb[cc], 0.f);
            if (LAST) {
                *(float4*)(outext + row * DD + ct * 4) = *(float4*)oo;
            } else {
                float ns = g_ns[row];   // pre-scale for the next layer's gather
                __half2 p0 = __floats2half2_rn(oo[0] * ns, oo[1] * ns);
                __half2 p1 = __floats2half2_rn(oo[2] * ns, oo[3] * ns);
                uint2 pk;
                pk.x = *(unsigned int*)&p0;
                pk.y = *(unsigned int*)&p1;
                *(uint2*)(g_hx + row * DD + ct * 4) = pk;
            }
        }
    }
}

// ---------------- launch ------------------------------------------------------
extern "C" void kernel_launch(void* const* d_in, const int* in_sizes, int n_in,
                              void* d_out, int out_size) {
    const float* h   = (const float*)d_in[0];
    const void*  src = d_in[1];
    const void*  dst = d_in[2];
    const float* Wl[3] = { (const float*)d_in[3], (const float*)d_in[5], (const float*)d_in[7] };
    const float* Bl[3] = { (const float*)d_in[4], (const float*)d_in[6], (const float*)d_in[8] };

    k_init<<<NB, 256>>>(src, dst);
    k_deg<<<(NE + 255) / 256, 256>>>(src, dst);
    k_norm_bsum<<<NB, 256>>>();
    k_offsets<<<NB, 256>>>();
    k_fill<<<(NE + 255) / 256, 256>>>(src, dst);

    int gblk = (NN * 32 + 255) / 256;   // one warp per node
    int mblk = (NN + 31) / 32;          // 32-row GEMM tiles
    // Layer 0: gather raw fp32 h with per-edge norm_src; GEMM writes fp16 g_hx.
    k_gather<0><<<gblk, 256>>>(h);
    k_gemm<0><<<mblk, 192>>>(Wl[0], Bl[0], nullptr);
    // Layer 1 (fp16 g_hx -> g_m -> fp16 g_hx; separate launches = no hazard)
    k_gather<1><<<gblk, 256>>>(nullptr);
    k_gemm<0><<<mblk, 192>>>(Wl[1], Bl[1], nullptr);
    // Layer 2 -> external fp32 output
    k_gather<1><<<gblk, 256>>>(nullptr);
    k_gemm<1><<<mblk, 192>>>(Wl[2], Bl[2], (float*)d_out);
}